// round 7
// baseline (speedup 1.0000x reference)
#include <cuda_runtime.h>
#include <mma.h>
#include <cstdint>

using namespace nvcuda;

namespace {
constexpr int NPTS = 262144;
constexpr int CHN  = 96;
constexpr int KOFF = 27;
constexpr int MT   = 128;        // rows per CTA tile
constexpr int NTHR = 256;        // 8 warps, 16 rows each
constexpr int LDA  = 100;        // padded ld (floats) for A tile
constexpr int BLD  = 100;        // padded ld (floats) for B tile
constexpr int QROW = CHN / 4;    // 24 float4 chunks per row
constexpr int SMEM_BYTES = (MT * LDA + CHN * BLD) * 4;  // 89600 B -> 2 CTAs/SM
}

__device__ float g_scratch[(size_t)NPTS * CHN];          // conv1 output (tf32-rounded)
__device__ float g_rfeats [(size_t)NPTS * CHN];          // feats, tf32-rounded
__device__ float g_wr     [2u * KOFF * CHN * CHN];       // W, tf32-rounded

// ---------------------------------------------------------------------------
__device__ __forceinline__ uint32_t smem_u32(const void* p) {
    uint32_t a;
    asm("{ .reg .u64 t; cvta.to.shared.u64 t, %1; cvt.u32.u64 %0, t; }" : "=r"(a) : "l"(p));
    return a;
}
__device__ __forceinline__ float to_tf32(float x) {
    float r; asm("cvt.rna.tf32.f32 %0, %1;" : "=f"(r) : "f"(x)); return r;
}
__device__ __forceinline__ void cp_async16(uint32_t dst, const void* src, int src_bytes) {
    asm volatile("cp.async.ca.shared.global [%0], [%1], 16, %2;"
                 :: "r"(dst), "l"(src), "r"(src_bytes) : "memory");
}
__device__ __forceinline__ void cp_commit_wait_all() {
    asm volatile("cp.async.commit_group;\n\tcp.async.wait_group 0;" ::: "memory");
}

// ---------------------------------------------------------------------------
// Prep: elementwise tf32 rounding (float4 vectorized)
// ---------------------------------------------------------------------------
__global__ void round_kernel(const float4* __restrict__ src, float4* __restrict__ dst, int n4) {
    for (int i = blockIdx.x * blockDim.x + threadIdx.x; i < n4; i += gridDim.x * blockDim.x) {
        float4 v = src[i];
        v.x = to_tf32(v.x); v.y = to_tf32(v.y); v.z = to_tf32(v.z); v.w = to_tf32(v.w);
        dst[i] = v;
    }
}

// ---------------------------------------------------------------------------
// Conv kernel: per CTA 128 rows, loop over 27 offsets, wmma tf32 16x16x8.
// 2 CTAs per SM: independent barriers overlap gather latency with MMA.
// ---------------------------------------------------------------------------
template<bool PASS2>
__global__ __launch_bounds__(NTHR, 2)
void conv_kernel(const float* __restrict__ fin,      // tf32-rounded conv input [N,CH]
                 const float* __restrict__ resid,    // original feats (pass2)
                 const int*   __restrict__ nidx,     // [K,N]
                 const int*   __restrict__ nmask,    // [K,N] (bool as int32)
                 const float* __restrict__ wr,       // tf32-rounded W [27][CH][CH]
                 const float* __restrict__ bias,
                 const float* __restrict__ alpha,
                 float* __restrict__ out)
{
    extern __shared__ float smem[];
    float* sA = smem;                 // [MT][LDA]
    float* sB = smem + MT * LDA;      // [CH][BLD]
    const uint32_t sAu = smem_u32(sA);
    const uint32_t sBu = smem_u32(sB);

    const int tid  = threadIdx.x;
    const int warp = tid >> 5;
    const int row0 = blockIdx.x * MT;

    wmma::fragment<wmma::accumulator, 16, 16, 8, float> acc[6];
#pragma unroll
    for (int i = 0; i < 6; i++) wmma::fill_fragment(acc[i], 0.0f);

    for (int k = 0; k < KOFF; k++) {
        // ---- stage A: two threads per row via cp.async (zfill when masked) ----
        {
            const int row  = tid >> 1;          // 0..127
            const int half = tid & 1;
            const int r  = row0 + row;
            const int nb = nidx [(size_t)k * NPTS + r];
            const int m  = nmask[(size_t)k * NPTS + r];
            const int sz = m ? 16 : 0;
            const char* src = (const char*)(fin + (size_t)nb * CHN) + half * 192;
            const uint32_t dst = sAu + row * (LDA * 4) + half * 192;
#pragma unroll
            for (int q = 0; q < QROW / 2; q++)
                cp_async16(dst + q * 16, src + q * 16, sz);
        }
        // ---- stage B: W[k] rows into padded smem ----
        {
            const char* wk = (const char*)(wr + (size_t)k * CHN * CHN);
#pragma unroll
            for (int j = 0; j < 9; j++) {
                const int i = tid + j * NTHR;           // 0..2303
                const int row = i / QROW, q = i % QROW;
                cp_async16(sBu + row * (BLD * 4) + q * 16, wk + row * (CHN * 4) + q * 16, 16);
            }
        }
        cp_commit_wait_all();
        __syncthreads();

        // ---- MMA: warp tile 16 rows x 96 cols ----
        const float* aBase = sA + (warp * 16) * LDA;
#pragma unroll
        for (int kk = 0; kk < CHN / 8; kk++) {
            wmma::fragment<wmma::matrix_a, 16, 16, 8, wmma::precision::tf32, wmma::row_major> af;
            wmma::load_matrix_sync(af, aBase + kk * 8, LDA);
#pragma unroll
            for (int n = 0; n < 6; n++) {
                wmma::fragment<wmma::matrix_b, 16, 16, 8, wmma::precision::tf32, wmma::row_major> bf;
                wmma::load_matrix_sync(bf, sB + (kk * 8) * BLD + n * 16, BLD);
                wmma::mma_sync(acc[n], af, bf, acc[n]);
            }
        }
        __syncthreads();   // MMA reads done before next k overwrites sA/sB
    }

    // ---- epilogue: park accumulators in sA, then bias/residual/PReLU ----
    {
        float* oBase = sA + (warp * 16) * LDA;
#pragma unroll
        for (int n = 0; n < 6; n++)
            wmma::store_matrix_sync(oBase + n * 16, acc[n], LDA, wmma::mem_row_major);
    }
    __syncthreads();

    const float av = __ldg(alpha);
#pragma unroll 1
    for (int i = tid; i < MT * QROW; i += NTHR) {
        const int row = i / QROW;
        const int q   = i % QROW;
        const int r   = row0 + row;
        float4 v  = *reinterpret_cast<const float4*>(sA + row * LDA + q * 4);
        float4 bv = reinterpret_cast<const float4*>(bias)[q];
        v.x += bv.x; v.y += bv.y; v.z += bv.z; v.w += bv.w;
        if (PASS2) {
            float4 f = *reinterpret_cast<const float4*>(resid + (size_t)r * CHN + q * 4);
            v.x += f.x; v.y += f.y; v.z += f.z; v.w += f.w;
        }
        v.x = (v.x > 0.f) ? v.x : av * v.x;
        v.y = (v.y > 0.f) ? v.y : av * v.y;
        v.z = (v.z > 0.f) ? v.z : av * v.z;
        v.w = (v.w > 0.f) ? v.w : av * v.w;
        if (!PASS2) {   // conv2 will consume this as tf32 operands: round now
            v.x = to_tf32(v.x); v.y = to_tf32(v.y);
            v.z = to_tf32(v.z); v.w = to_tf32(v.w);
        }
        *reinterpret_cast<float4*>(out + (size_t)r * CHN + q * 4) = v;
    }
}

// ---------------------------------------------------------------------------
extern "C" void kernel_launch(void* const* d_in, const int* in_sizes, int n_in,
                              void* d_out, int out_size)
{
    const float* feats = (const float*)d_in[0];
    const int*   nidx  = (const int*)d_in[1];
    const int*   nmask = (const int*)d_in[2];
    const float* W1    = (const float*)d_in[3];
    const float* b1    = (const float*)d_in[4];
    const float* a1    = (const float*)d_in[5];
    const float* W2    = (const float*)d_in[6];
    const float* b2    = (const float*)d_in[7];
    const float* a2    = (const float*)d_in[8];
    float* out = (float*)d_out;

    float *scratch = nullptr, *rfeats = nullptr, *wr = nullptr;
    cudaGetSymbolAddress((void**)&scratch, g_scratch);
    cudaGetSymbolAddress((void**)&rfeats,  g_rfeats);
    cudaGetSymbolAddress((void**)&wr,      g_wr);

    cudaFuncSetAttribute(conv_kernel<false>,
                         cudaFuncAttributeMaxDynamicSharedMemorySize, SMEM_BYTES);
    cudaFuncSetAttribute(conv_kernel<true>,
                         cudaFuncAttributeMaxDynamicSharedMemorySize, SMEM_BYTES);

    const int WN4 = KOFF * CHN * CHN / 4;             // 62208
    round_kernel<<<64, 256>>>((const float4*)W1, (float4*)wr, WN4);
    round_kernel<<<64, 256>>>((const float4*)W2, (float4*)(wr + (size_t)KOFF * CHN * CHN), WN4);
    round_kernel<<<2048, 256>>>((const float4*)feats, (float4*)rfeats, NPTS * CHN / 4);

    const int grid = NPTS / MT;  // 2048
    conv_kernel<false><<<grid, NTHR, SMEM_BYTES>>>(
        rfeats, nullptr, nidx, nmask, wr, b1, a1, scratch);
    conv_kernel<true><<<grid, NTHR, SMEM_BYTES>>>(
        scratch, feats, nidx, nmask, wr + (size_t)KOFF * CHN * CHN, b2, a2, out);
}

// round 8
// speedup vs baseline: 1.0753x; 1.0753x over previous
#include <cuda_runtime.h>
#include <mma.h>
#include <cstdint>

using namespace nvcuda;

namespace {
constexpr int NPTS = 262144;
constexpr int CHN  = 96;
constexpr int KOFF = 27;
constexpr int MT   = 256;        // rows per CTA tile
constexpr int NTHR = 256;        // 8 warps, 32 rows each
constexpr int LDA  = 100;        // padded ld (floats) for A tile
constexpr int BLD  = 100;        // padded ld (floats) for B tile
constexpr int QROW = CHN / 4;    // 24 float4 chunks per row
constexpr int SMEM_BYTES = (MT * LDA + 2 * CHN * BLD) * 4;  // 179200 B
}

__device__ float g_scratch[(size_t)NPTS * CHN];          // conv1 output (tf32-rounded)
__device__ float g_rfeats [(size_t)NPTS * CHN];          // feats, tf32-rounded
__device__ float g_wr     [2u * KOFF * CHN * CHN];       // W, tf32-rounded

// ---------------------------------------------------------------------------
__device__ __forceinline__ uint32_t smem_u32(const void* p) {
    uint32_t a;
    asm("{ .reg .u64 t; cvta.to.shared.u64 t, %1; cvt.u32.u64 %0, t; }" : "=r"(a) : "l"(p));
    return a;
}
__device__ __forceinline__ float to_tf32(float x) {
    float r; asm("cvt.rna.tf32.f32 %0, %1;" : "=f"(r) : "f"(x)); return r;
}
__device__ __forceinline__ void cp_async16(uint32_t dst, const void* src, int src_bytes) {
    asm volatile("cp.async.ca.shared.global [%0], [%1], 16, %2;"
                 :: "r"(dst), "l"(src), "r"(src_bytes) : "memory");
}
__device__ __forceinline__ void cp_commit() {
    asm volatile("cp.async.commit_group;" ::: "memory");
}
__device__ __forceinline__ void cp_wait_all() {
    asm volatile("cp.async.wait_group 0;" ::: "memory");
}

// ---------------------------------------------------------------------------
// Prep: elementwise tf32 rounding (float4 vectorized)
// ---------------------------------------------------------------------------
__global__ void round_kernel(const float4* __restrict__ src, float4* __restrict__ dst, int n4) {
    for (int i = blockIdx.x * blockDim.x + threadIdx.x; i < n4; i += gridDim.x * blockDim.x) {
        float4 v = src[i];
        v.x = to_tf32(v.x); v.y = to_tf32(v.y); v.z = to_tf32(v.z); v.w = to_tf32(v.w);
        dst[i] = v;
    }
}

// ---------------------------------------------------------------------------
// Conv kernel: MT=256 rows/CTA, 8 warps x 32 rows, pipelined k-loop:
//   B(k+1) prefetched (double-buffered) before MMA(k);
//   A(k+1) self-gathered per-warp into its own rows after its MMA(k).
// ---------------------------------------------------------------------------
template<bool PASS2>
__global__ __launch_bounds__(NTHR, 1)
void conv_kernel(const float* __restrict__ fin,      // tf32-rounded conv input [N,CH]
                 const float* __restrict__ resid,    // original feats (pass2)
                 const int*   __restrict__ nidx,     // [K,N]
                 const int*   __restrict__ nmask,    // [K,N] (bool as int32)
                 const float* __restrict__ wr,       // tf32-rounded W [27][CH][CH]
                 const float* __restrict__ bias,
                 const float* __restrict__ alpha,
                 float* __restrict__ out)
{
    extern __shared__ float smem[];
    float* sA  = smem;                        // [MT][LDA]
    float* sB0 = smem + MT * LDA;             // [CH][BLD] buffer 0
    float* sB1 = sB0 + CHN * BLD;             // [CH][BLD] buffer 1
    const uint32_t sAu  = smem_u32(sA);
    const uint32_t sB0u = smem_u32(sB0);
    const uint32_t sB1u = smem_u32(sB1);

    const int tid  = threadIdx.x;
    const int warp = tid >> 5;
    const int lane = tid & 31;
    const int row0 = blockIdx.x * MT;

    // this thread's gather row (one row per lane within the warp's 32 rows)
    const int myRowLocal = warp * 32 + lane;
    const int myRow      = row0 + myRowLocal;
    const uint32_t myDst = sAu + myRowLocal * (LDA * 4);

    wmma::fragment<wmma::accumulator, 16, 16, 8, float> acc[12];
#pragma unroll
    for (int i = 0; i < 12; i++) wmma::fill_fragment(acc[i], 0.0f);

    // ---- prologue: stage A(0) + B(0) ----
    {
        const int nb = nidx [(size_t)0 * NPTS + myRow];
        const int m  = nmask[(size_t)0 * NPTS + myRow];
        const int sz = m ? 16 : 0;
        const char* src = (const char*)(fin + (size_t)nb * CHN);
#pragma unroll
        for (int q = 0; q < QROW; q++)
            cp_async16(myDst + q * 16, src + q * 16, sz);

        const char* wk = (const char*)wr;  // k = 0
#pragma unroll
        for (int j = 0; j < 9; j++) {
            const int i = tid + j * NTHR;
            const int row = i / QROW, q = i % QROW;
            cp_async16(sB0u + row * (BLD * 4) + q * 16, wk + row * (CHN * 4) + q * 16, 16);
        }
        cp_commit();
        cp_wait_all();
        __syncthreads();
    }

    for (int k = 0; k < KOFF; k++) {
        const bool more = (k + 1 < KOFF);
        const float* sBcur = (k & 1) ? sB1 : sB0;
        const uint32_t sBnxt = (k & 1) ? sB0u : sB1u;

        // ---- prefetch B(k+1) into the other buffer (hidden behind MMA) ----
        if (more) {
            const char* wk = (const char*)(wr + (size_t)(k + 1) * CHN * CHN);
#pragma unroll
            for (int j = 0; j < 9; j++) {
                const int i = tid + j * NTHR;
                const int row = i / QROW, q = i % QROW;
                cp_async16(sBnxt + row * (BLD * 4) + q * 16, wk + row * (CHN * 4) + q * 16, 16);
            }
            cp_commit();
        }
        // ---- prefetch next gather index/mask into registers ----
        int nbN = 0, szN = 0;
        if (more) {
            nbN = nidx [(size_t)(k + 1) * NPTS + myRow];
            szN = nmask[(size_t)(k + 1) * NPTS + myRow] ? 16 : 0;
        }

        // ---- MMA: warp tile 32 rows x 96 cols, B frag reused for 2 A blocks ----
        const float* aBase = sA + (warp * 32) * LDA;
#pragma unroll
        for (int kk = 0; kk < CHN / 8; kk++) {
            wmma::fragment<wmma::matrix_a, 16, 16, 8, wmma::precision::tf32, wmma::row_major> a0, a1;
            wmma::load_matrix_sync(a0, aBase + kk * 8, LDA);
            wmma::load_matrix_sync(a1, aBase + 16 * LDA + kk * 8, LDA);
#pragma unroll
            for (int n = 0; n < 6; n++) {
                wmma::fragment<wmma::matrix_b, 16, 16, 8, wmma::precision::tf32, wmma::row_major> bf;
                wmma::load_matrix_sync(bf, sBcur + (kk * 8) * BLD + n * 16, BLD);
                wmma::mma_sync(acc[n],     a0, bf, acc[n]);
                wmma::mma_sync(acc[6 + n], a1, bf, acc[6 + n]);
            }
        }

        // ---- self-gather A(k+1) into this warp's own rows (after own MMA) ----
        if (more) {
            const char* src = (const char*)(fin + (size_t)nbN * CHN);
#pragma unroll
            for (int q = 0; q < QROW; q++)
                cp_async16(myDst + q * 16, src + q * 16, szN);
            cp_commit();
            cp_wait_all();
            __syncthreads();
        }
    }

    // ---- epilogue: park accumulators in sA, then bias/residual/PReLU ----
    {
        float* oBase = sA + (warp * 32) * LDA;
#pragma unroll
        for (int n = 0; n < 6; n++) {
            wmma::store_matrix_sync(oBase + n * 16,            acc[n],     LDA, wmma::mem_row_major);
            wmma::store_matrix_sync(oBase + 16 * LDA + n * 16, acc[6 + n], LDA, wmma::mem_row_major);
        }
    }
    __syncthreads();

    const float av = __ldg(alpha);
#pragma unroll 1
    for (int i = tid; i < MT * QROW; i += NTHR) {
        const int row = i / QROW;
        const int q   = i % QROW;
        const int r   = row0 + row;
        float4 v  = *reinterpret_cast<const float4*>(sA + row * LDA + q * 4);
        float4 bv = reinterpret_cast<const float4*>(bias)[q];
        v.x += bv.x; v.y += bv.y; v.z += bv.z; v.w += bv.w;
        if (PASS2) {
            float4 f = *reinterpret_cast<const float4*>(resid + (size_t)r * CHN + q * 4);
            v.x += f.x; v.y += f.y; v.z += f.z; v.w += f.w;
        }
        v.x = (v.x > 0.f) ? v.x : av * v.x;
        v.y = (v.y > 0.f) ? v.y : av * v.y;
        v.z = (v.z > 0.f) ? v.z : av * v.z;
        v.w = (v.w > 0.f) ? v.w : av * v.w;
        if (!PASS2) {   // conv2 consumes this as tf32 operands: round now
            v.x = to_tf32(v.x); v.y = to_tf32(v.y);
            v.z = to_tf32(v.z); v.w = to_tf32(v.w);
        }
        *reinterpret_cast<float4*>(out + (size_t)r * CHN + q * 4) = v;
    }
}

// ---------------------------------------------------------------------------
extern "C" void kernel_launch(void* const* d_in, const int* in_sizes, int n_in,
                              void* d_out, int out_size)
{
    const float* feats = (const float*)d_in[0];
    const int*   nidx  = (const int*)d_in[1];
    const int*   nmask = (const int*)d_in[2];
    const float* W1    = (const float*)d_in[3];
    const float* b1    = (const float*)d_in[4];
    const float* a1    = (const float*)d_in[5];
    const float* W2    = (const float*)d_in[6];
    const float* b2    = (const float*)d_in[7];
    const float* a2    = (const float*)d_in[8];
    float* out = (float*)d_out;

    float *scratch = nullptr, *rfeats = nullptr, *wr = nullptr;
    cudaGetSymbolAddress((void**)&scratch, g_scratch);
    cudaGetSymbolAddress((void**)&rfeats,  g_rfeats);
    cudaGetSymbolAddress((void**)&wr,      g_wr);

    cudaFuncSetAttribute(conv_kernel<false>,
                         cudaFuncAttributeMaxDynamicSharedMemorySize, SMEM_BYTES);
    cudaFuncSetAttribute(conv_kernel<true>,
                         cudaFuncAttributeMaxDynamicSharedMemorySize, SMEM_BYTES);

    const int WN4 = KOFF * CHN * CHN / 4;             // 62208
    round_kernel<<<64, 256>>>((const float4*)W1, (float4*)wr, WN4);
    round_kernel<<<64, 256>>>((const float4*)W2, (float4*)(wr + (size_t)KOFF * CHN * CHN), WN4);
    round_kernel<<<2048, 256>>>((const float4*)feats, (float4*)rfeats, NPTS * CHN / 4);

    const int grid = NPTS / MT;  // 1024
    conv_kernel<false><<<grid, NTHR, SMEM_BYTES>>>(
        rfeats, nullptr, nidx, nmask, wr, b1, a1, scratch);
    conv_kernel<true><<<grid, NTHR, SMEM_BYTES>>>(
        scratch, feats, nidx, nmask, wr + (size_t)KOFF * CHN * CHN, b2, a2, out);
}

// round 11
// speedup vs baseline: 3.5349x; 3.2874x over previous
#include <cuda_runtime.h>
#include <cuda_fp16.h>
#include <mma.h>
#include <cstdint>

using namespace nvcuda;

namespace {
constexpr int NPTS = 262144;
constexpr int CHN  = 96;
constexpr int KOFF = 27;
constexpr int MT   = 256;        // rows per CTA tile
constexpr int NTHR = 256;        // 8 warps, 32 rows each
constexpr int LDH  = 104;        // padded ld (halfs) for A and B tiles (208 B)
constexpr int LDF  = 100;        // padded ld (floats) for epilogue parking
constexpr int QROW = 12;         // 16B chunks per 96-half row
// staging: A 256*104*2 + B 2*96*104*2 = 53248 + 39936 = 93184
// parking: 256*100*4 = 102400  (overlaps staging after last MMA)
constexpr int SMEM_BYTES = MT * LDF * 4;   // 102400 B -> 2 CTAs/SM
constexpr int A_BYTES  = MT * LDH * 2;     // 53248
constexpr int B_BYTES  = CHN * LDH * 2;    // 19968
}

__device__ __half g_scratch[(size_t)NPTS * CHN];         // conv1 output (fp16)
__device__ __half g_hfeats [(size_t)NPTS * CHN];         // feats, fp16
__device__ __half g_wh     [2u * KOFF * CHN * CHN];      // W, fp16

// ---------------------------------------------------------------------------
__device__ __forceinline__ uint32_t smem_u32(const void* p) {
    uint32_t a;
    asm("{ .reg .u64 t; cvta.to.shared.u64 t, %1; cvt.u32.u64 %0, t; }" : "=r"(a) : "l"(p));
    return a;
}
__device__ __forceinline__ void cp_async16(uint32_t dst, const void* src, int src_bytes) {
    asm volatile("cp.async.ca.shared.global [%0], [%1], 16, %2;"
                 :: "r"(dst), "l"(src), "r"(src_bytes) : "memory");
}
__device__ __forceinline__ void cp_commit() {
    asm volatile("cp.async.commit_group;" ::: "memory");
}
__device__ __forceinline__ void cp_wait_all() {
    asm volatile("cp.async.wait_group 0;" ::: "memory");
}

// ---------------------------------------------------------------------------
// Prep: fp32 -> fp16 conversion (float2 -> half2)
// ---------------------------------------------------------------------------
__global__ void tohalf_kernel(const float2* __restrict__ src, __half2* __restrict__ dst, int n2) {
    for (int i = blockIdx.x * blockDim.x + threadIdx.x; i < n2; i += gridDim.x * blockDim.x)
        dst[i] = __float22half2_rn(src[i]);
}

// ---------------------------------------------------------------------------
// Conv kernel: MT=256 rows/CTA, 8 warps x 32 rows, fp16 m16n16k16 wmma,
// pipelined k-loop (B double-buffered prefetch, per-warp A self-gather).
// OutT = __half for conv1 (feeds conv2), float for conv2 (final output).
// ---------------------------------------------------------------------------
template<bool PASS2, typename OutT>
__global__ __launch_bounds__(NTHR, 2)
void conv_kernel(const __half* __restrict__ fin,     // fp16 conv input [N,CH]
                 const float* __restrict__ resid,    // original fp32 feats (pass2)
                 const int*   __restrict__ nidx,     // [K,N]
                 const int*   __restrict__ nmask,    // [K,N] (bool as int32)
                 const __half* __restrict__ wh,      // fp16 W [27][CH][CH]
                 const float* __restrict__ bias,
                 const float* __restrict__ alpha,
                 OutT* __restrict__ out)             // [N,CH]
{
    extern __shared__ char smem[];
    __half* sA  = (__half*)smem;                       // [MT][LDH]
    __half* sB0 = (__half*)(smem + A_BYTES);           // [CH][LDH]
    __half* sB1 = (__half*)(smem + A_BYTES + B_BYTES); // [CH][LDH]
    float*  sPark = (float*)smem;                      // [MT][LDF] (after MMAs)
    const uint32_t sAu  = smem_u32(sA);
    const uint32_t sB0u = smem_u32(sB0);
    const uint32_t sB1u = smem_u32(sB1);

    const int tid  = threadIdx.x;
    const int warp = tid >> 5;
    const int lane = tid & 31;
    const int row0 = blockIdx.x * MT;

    // per-lane gather row: each lane owns one of its warp's 32 rows
    const int myRowLocal = warp * 32 + lane;
    const int myRow      = row0 + myRowLocal;
    const uint32_t myDst = sAu + myRowLocal * (LDH * 2);

    wmma::fragment<wmma::accumulator, 16, 16, 16, float> acc[12];
#pragma unroll
    for (int i = 0; i < 12; i++) wmma::fill_fragment(acc[i], 0.0f);

    // ---- prologue: stage A(0) + B(0) ----
    {
        const int nb = nidx [myRow];
        const int sz = nmask[myRow] ? 16 : 0;
        const char* src = (const char*)(fin + (size_t)nb * CHN);
#pragma unroll
        for (int q = 0; q < QROW; q++)
            cp_async16(myDst + q * 16, src + q * 16, sz);

        const char* wk = (const char*)wh;  // k = 0
#pragma unroll
        for (int j = 0; j < 5; j++) {
            const int i = tid + j * NTHR;            // 0..1279, need 1152
            if (i < CHN * QROW) {
                const int row = i / QROW, q = i % QROW;
                cp_async16(sB0u + row * (LDH * 2) + q * 16, wk + row * (CHN * 2) + q * 16, 16);
            }
        }
        cp_commit();
        cp_wait_all();
        __syncthreads();
    }

    for (int k = 0; k < KOFF; k++) {
        const bool more = (k + 1 < KOFF);
        const __half* sBcur  = (k & 1) ? sB1 : sB0;
        const uint32_t sBnxt = (k & 1) ? sB0u : sB1u;

        // ---- prefetch B(k+1) into the other buffer (hidden behind MMA) ----
        if (more) {
            const char* wk = (const char*)(wh + (size_t)(k + 1) * CHN * CHN);
#pragma unroll
            for (int j = 0; j < 5; j++) {
                const int i = tid + j * NTHR;
                if (i < CHN * QROW) {
                    const int row = i / QROW, q = i % QROW;
                    cp_async16(sBnxt + row * (LDH * 2) + q * 16, wk + row * (CHN * 2) + q * 16, 16);
                }
            }
            cp_commit();
        }
        // ---- prefetch next gather index/mask into registers ----
        int nbN = 0, szN = 0;
        if (more) {
            nbN = nidx [(size_t)(k + 1) * NPTS + myRow];
            szN = nmask[(size_t)(k + 1) * NPTS + myRow] ? 16 : 0;
        }

        // ---- MMA: warp tile 32 rows x 96 cols, fp16 K=16 steps ----
        const __half* aBase = sA + (warp * 32) * LDH;
#pragma unroll
        for (int kk = 0; kk < CHN / 16; kk++) {
            wmma::fragment<wmma::matrix_a, 16, 16, 16, __half, wmma::row_major> a0, a1;
            wmma::load_matrix_sync(a0, aBase + kk * 16, LDH);
            wmma::load_matrix_sync(a1, aBase + 16 * LDH + kk * 16, LDH);
#pragma unroll
            for (int n = 0; n < 6; n++) {
                wmma::fragment<wmma::matrix_b, 16, 16, 16, __half, wmma::row_major> bf;
                wmma::load_matrix_sync(bf, sBcur + (kk * 16) * LDH + n * 16, LDH);
                wmma::mma_sync(acc[n],     a0, bf, acc[n]);
                wmma::mma_sync(acc[6 + n], a1, bf, acc[6 + n]);
            }
        }

        // ---- self-gather A(k+1) into this warp's own rows ----
        if (more) {
            const char* src = (const char*)(fin + (size_t)nbN * CHN);
#pragma unroll
            for (int q = 0; q < QROW; q++)
                cp_async16(myDst + q * 16, src + q * 16, szN);
            cp_commit();
            cp_wait_all();
            __syncthreads();
        }
    }

    // ---- epilogue: park accumulators (fp32) over the staging smem ----
    __syncthreads();
    {
        float* oBase = sPark + (warp * 32) * LDF;
#pragma unroll
        for (int n = 0; n < 6; n++) {
            wmma::store_matrix_sync(oBase + n * 16,            acc[n],     LDF, wmma::mem_row_major);
            wmma::store_matrix_sync(oBase + 16 * LDF + n * 16, acc[6 + n], LDF, wmma::mem_row_major);
        }
    }
    __syncthreads();

    const float av = __ldg(alpha);
#pragma unroll 1
    for (int i = tid; i < MT * (CHN / 4); i += NTHR) {
        const int row = i / (CHN / 4);
        const int q   = i % (CHN / 4);
        const int r   = row0 + row;
        float4 v  = *reinterpret_cast<const float4*>(sPark + row * LDF + q * 4);
        float4 bv = reinterpret_cast<const float4*>(bias)[q];
        v.x += bv.x; v.y += bv.y; v.z += bv.z; v.w += bv.w;
        if (PASS2) {
            float4 f = *reinterpret_cast<const float4*>(resid + (size_t)r * CHN + q * 4);
            v.x += f.x; v.y += f.y; v.z += f.z; v.w += f.w;
        }
        v.x = (v.x > 0.f) ? v.x : av * v.x;
        v.y = (v.y > 0.f) ? v.y : av * v.y;
        v.z = (v.z > 0.f) ? v.z : av * v.z;
        v.w = (v.w > 0.f) ? v.w : av * v.w;
        if (PASS2) {
            // final output: fp32
            *reinterpret_cast<float4*>((float*)out + (size_t)r * CHN + q * 4) = v;
        } else {
            // conv1 output consumed by conv2 as fp16 operands
            __half2 h0 = __floats2half2_rn(v.x, v.y);
            __half2 h1 = __floats2half2_rn(v.z, v.w);
            __half2* dst = reinterpret_cast<__half2*>((__half*)out + (size_t)r * CHN + q * 4);
            dst[0] = h0; dst[1] = h1;
        }
    }
}

// ---------------------------------------------------------------------------
extern "C" void kernel_launch(void* const* d_in, const int* in_sizes, int n_in,
                              void* d_out, int out_size)
{
    const float* feats = (const float*)d_in[0];
    const int*   nidx  = (const int*)d_in[1];
    const int*   nmask = (const int*)d_in[2];
    const float* W1    = (const float*)d_in[3];
    const float* b1    = (const float*)d_in[4];
    const float* a1    = (const float*)d_in[5];
    const float* W2    = (const float*)d_in[6];
    const float* b2    = (const float*)d_in[7];
    const float* a2    = (const float*)d_in[8];
    float* out = (float*)d_out;

    __half *scratch = nullptr, *hfeats = nullptr, *wh = nullptr;
    cudaGetSymbolAddress((void**)&scratch, g_scratch);
    cudaGetSymbolAddress((void**)&hfeats,  g_hfeats);
    cudaGetSymbolAddress((void**)&wh,      g_wh);

    cudaFuncSetAttribute((const void*)conv_kernel<false, __half>,
                         cudaFuncAttributeMaxDynamicSharedMemorySize, SMEM_BYTES);
    cudaFuncSetAttribute((const void*)conv_kernel<true, float>,
                         cudaFuncAttributeMaxDynamicSharedMemorySize, SMEM_BYTES);

    const int WN2 = KOFF * CHN * CHN / 2;             // 124416
    tohalf_kernel<<<128, 256>>>((const float2*)W1, (__half2*)wh, WN2);
    tohalf_kernel<<<128, 256>>>((const float2*)W2, (__half2*)(wh + (size_t)KOFF * CHN * CHN), WN2);
    tohalf_kernel<<<2048, 256>>>((const float2*)feats, (__half2*)hfeats, NPTS * CHN / 2);

    const int grid = NPTS / MT;  // 1024
    conv_kernel<false, __half><<<grid, NTHR, SMEM_BYTES>>>(
        hfeats, nullptr, nidx, nmask, wh, b1, a1, scratch);
    conv_kernel<true, float><<<grid, NTHR, SMEM_BYTES>>>(
        scratch, feats, nidx, nmask, wh + (size_t)KOFF * CHN * CHN, b2, a2, out);
}

// round 12
// speedup vs baseline: 3.5513x; 1.0046x over previous
#include <cuda_runtime.h>
#include <cuda_fp16.h>
#include <mma.h>
#include <cstdint>

using namespace nvcuda;

namespace {
constexpr int NPTS = 262144;
constexpr int CHN  = 96;
constexpr int KOFF = 27;
constexpr int MT   = 512;        // rows per CTA tile
constexpr int NTHR = 256;        // 8 warps, 64 rows each
constexpr int LDH  = 104;        // padded ld (halfs), 208 B rows (conflict-free)
constexpr int QROW = 12;         // 16B chunks per 96-half row
constexpr int A_BYTES = MT * LDH * 2;     // 106496
constexpr int B_BYTES = CHN * LDH * 2;    // 19968
constexpr int SMEM_BYTES = A_BYTES + 2 * B_BYTES;  // 146432 -> 1 CTA/SM
}

__device__ float  g_dump   [(size_t)NPTS * CHN];     // raw conv accumulators (fp32)
__device__ __half g_hfeats [(size_t)NPTS * CHN];     // feats, fp16
__device__ __half g_scr    [(size_t)NPTS * CHN];     // conv1 activations, fp16
__device__ __half g_wh     [2u * KOFF * CHN * CHN];  // W, fp16

// ---------------------------------------------------------------------------
__device__ __forceinline__ uint32_t smem_u32(const void* p) {
    uint32_t a;
    asm("{ .reg .u64 t; cvta.to.shared.u64 t, %1; cvt.u32.u64 %0, t; }" : "=r"(a) : "l"(p));
    return a;
}
__device__ __forceinline__ void cp_async16(uint32_t dst, const void* src, int src_bytes) {
    asm volatile("cp.async.ca.shared.global [%0], [%1], 16, %2;"
                 :: "r"(dst), "l"(src), "r"(src_bytes) : "memory");
}
__device__ __forceinline__ void cp_commit() {
    asm volatile("cp.async.commit_group;" ::: "memory");
}
__device__ __forceinline__ void cp_wait_all() {
    asm volatile("cp.async.wait_group 0;" ::: "memory");
}

// ---------------------------------------------------------------------------
// Prep: fp32 -> fp16
// ---------------------------------------------------------------------------
__global__ void tohalf_kernel(const float2* __restrict__ src, __half2* __restrict__ dst, int n2) {
    for (int i = blockIdx.x * blockDim.x + threadIdx.x; i < n2; i += gridDim.x * blockDim.x)
        dst[i] = __float22half2_rn(src[i]);
}

// ---------------------------------------------------------------------------
// Conv: MT=512 rows/CTA, 8 warps x 64 rows, fp16 m16n16k16, pipelined k-loop.
// Accumulators dumped raw (no bias) to gmem fp32.
// ---------------------------------------------------------------------------
__global__ __launch_bounds__(NTHR, 1)
void conv_kernel(const __half* __restrict__ fin,     // fp16 conv input [N,CH]
                 const int*    __restrict__ nidx,    // [K,N]
                 const int*    __restrict__ nmask,   // [K,N]
                 const __half* __restrict__ wh,      // fp16 W [27][CH][CH]
                 float* __restrict__ dump)           // [N,CH] raw accumulators
{
    extern __shared__ char smem[];
    __half* sA  = (__half*)smem;                       // [MT][LDH]
    __half* sB0 = (__half*)(smem + A_BYTES);           // [CH][LDH]
    __half* sB1 = (__half*)(smem + A_BYTES + B_BYTES); // [CH][LDH]
    const uint32_t sAu  = smem_u32(sA);
    const uint32_t sB0u = smem_u32(sB0);
    const uint32_t sB1u = smem_u32(sB1);

    const int tid  = threadIdx.x;
    const int warp = tid >> 5;
    const int lane = tid & 31;
    const int row0 = blockIdx.x * MT;

    // each lane owns 2 of its warp's 64 rows
    const int rl0 = warp * 64 + lane;
    const int rl1 = rl0 + 32;
    const int gr0 = row0 + rl0;
    const int gr1 = row0 + rl1;
    const uint32_t dst0 = sAu + rl0 * (LDH * 2);
    const uint32_t dst1 = sAu + rl1 * (LDH * 2);

    wmma::fragment<wmma::accumulator, 16, 16, 16, float> acc[24];
#pragma unroll
    for (int i = 0; i < 24; i++) wmma::fill_fragment(acc[i], 0.0f);

    // ---- prologue: stage A(0) + B(0) ----
    {
        const int nb0 = nidx[gr0], nb1 = nidx[gr1];
        const int sz0 = nmask[gr0] ? 16 : 0;
        const int sz1 = nmask[gr1] ? 16 : 0;
        const char* s0 = (const char*)(fin + (size_t)nb0 * CHN);
        const char* s1 = (const char*)(fin + (size_t)nb1 * CHN);
#pragma unroll
        for (int q = 0; q < QROW; q++) {
            cp_async16(dst0 + q * 16, s0 + q * 16, sz0);
            cp_async16(dst1 + q * 16, s1 + q * 16, sz1);
        }
        const char* wk = (const char*)wh;  // k = 0
#pragma unroll
        for (int j = 0; j < 5; j++) {
            const int i = tid + j * NTHR;            // need 1152
            if (i < CHN * QROW) {
                const int row = i / QROW, q = i % QROW;
                cp_async16(sB0u + row * (LDH * 2) + q * 16, wk + row * (CHN * 2) + q * 16, 16);
            }
        }
        cp_commit();
        cp_wait_all();
        __syncthreads();
    }

    for (int k = 0; k < KOFF; k++) {
        const bool more = (k + 1 < KOFF);
        const __half* sBcur  = (k & 1) ? sB1 : sB0;
        const uint32_t sBnxt = (k & 1) ? sB0u : sB1u;

        // ---- prefetch B(k+1) (hidden behind MMA) ----
        if (more) {
            const char* wk = (const char*)(wh + (size_t)(k + 1) * CHN * CHN);
#pragma unroll
            for (int j = 0; j < 5; j++) {
                const int i = tid + j * NTHR;
                if (i < CHN * QROW) {
                    const int row = i / QROW, q = i % QROW;
                    cp_async16(sBnxt + row * (LDH * 2) + q * 16, wk + row * (CHN * 2) + q * 16, 16);
                }
            }
            cp_commit();
        }
        // ---- prefetch next gather indices ----
        int nb0 = 0, nb1 = 0, sz0 = 0, sz1 = 0;
        if (more) {
            const size_t o = (size_t)(k + 1) * NPTS;
            nb0 = nidx[o + gr0]; sz0 = nmask[o + gr0] ? 16 : 0;
            nb1 = nidx[o + gr1]; sz1 = nmask[o + gr1] ? 16 : 0;
        }

        // ---- MMA: warp tile 64 rows x 96 cols; each B frag feeds 4 A blocks ----
        const __half* aBase = sA + (warp * 64) * LDH;
#pragma unroll
        for (int kk = 0; kk < CHN / 16; kk++) {
            wmma::fragment<wmma::matrix_a, 16, 16, 16, __half, wmma::row_major> af[4];
#pragma unroll
            for (int b = 0; b < 4; b++)
                wmma::load_matrix_sync(af[b], aBase + (b * 16) * LDH + kk * 16, LDH);
#pragma unroll
            for (int n = 0; n < 6; n++) {
                wmma::fragment<wmma::matrix_b, 16, 16, 16, __half, wmma::row_major> bf;
                wmma::load_matrix_sync(bf, sBcur + (kk * 16) * LDH + n * 16, LDH);
#pragma unroll
                for (int b = 0; b < 4; b++)
                    wmma::mma_sync(acc[b * 6 + n], af[b], bf, acc[b * 6 + n]);
            }
        }

        // ---- self-gather A(k+1) into this warp's own rows ----
        if (more) {
            const char* s0 = (const char*)(fin + (size_t)nb0 * CHN);
            const char* s1 = (const char*)(fin + (size_t)nb1 * CHN);
#pragma unroll
            for (int q = 0; q < QROW; q++) {
                cp_async16(dst0 + q * 16, s0 + q * 16, sz0);
                cp_async16(dst1 + q * 16, s1 + q * 16, sz1);
            }
            cp_commit();
            cp_wait_all();
            __syncthreads();
        }
    }

    // ---- dump raw accumulators straight to gmem (DRAM is idle) ----
    {
        float* oBase = dump + (size_t)(row0 + warp * 64) * CHN;
#pragma unroll
        for (int b = 0; b < 4; b++)
#pragma unroll
            for (int n = 0; n < 6; n++)
                wmma::store_matrix_sync(oBase + (size_t)(b * 16) * CHN + n * 16,
                                        acc[b * 6 + n], CHN, wmma::mem_row_major);
    }
}

// ---------------------------------------------------------------------------
// Epilogue 1: fp32 dump -> bias+PReLU -> fp16 activations
// ---------------------------------------------------------------------------
__global__ void epi1_kernel(const float4* __restrict__ dump,
                            const float* __restrict__ bias,
                            const float* __restrict__ alpha,
                            uint2* __restrict__ outh)   // 4 halfs per uint2
{
    const float av = __ldg(alpha);
    const int n4 = NPTS * CHN / 4;
    for (int i = blockIdx.x * blockDim.x + threadIdx.x; i < n4; i += gridDim.x * blockDim.x) {
        const int q = i % (CHN / 4);
        float4 v  = dump[i];
        float4 bv = reinterpret_cast<const float4*>(bias)[q];
        v.x += bv.x; v.y += bv.y; v.z += bv.z; v.w += bv.w;
        v.x = (v.x > 0.f) ? v.x : av * v.x;
        v.y = (v.y > 0.f) ? v.y : av * v.y;
        v.z = (v.z > 0.f) ? v.z : av * v.z;
        v.w = (v.w > 0.f) ? v.w : av * v.w;
        __half2 h0 = __floats2half2_rn(v.x, v.y);
        __half2 h1 = __floats2half2_rn(v.z, v.w);
        uint2 o;
        o.x = *reinterpret_cast<uint32_t*>(&h0);
        o.y = *reinterpret_cast<uint32_t*>(&h1);
        outh[i] = o;
    }
}

// ---------------------------------------------------------------------------
// Epilogue 2: in-place on d_out: out = PReLU(out + b2 + feats, a2)
// ---------------------------------------------------------------------------
__global__ void epi2_kernel(float4* __restrict__ out,
                            const float4* __restrict__ feats,
                            const float* __restrict__ bias,
                            const float* __restrict__ alpha)
{
    const float av = __ldg(alpha);
    const int n4 = NPTS * CHN / 4;
    for (int i = blockIdx.x * blockDim.x + threadIdx.x; i < n4; i += gridDim.x * blockDim.x) {
        const int q = i % (CHN / 4);
        float4 v  = out[i];
        float4 f  = feats[i];
        float4 bv = reinterpret_cast<const float4*>(bias)[q];
        v.x += bv.x + f.x; v.y += bv.y + f.y; v.z += bv.z + f.z; v.w += bv.w + f.w;
        v.x = (v.x > 0.f) ? v.x : av * v.x;
        v.y = (v.y > 0.f) ? v.y : av * v.y;
        v.z = (v.z > 0.f) ? v.z : av * v.z;
        v.w = (v.w > 0.f) ? v.w : av * v.w;
        out[i] = v;
    }
}

// ---------------------------------------------------------------------------
extern "C" void kernel_launch(void* const* d_in, const int* in_sizes, int n_in,
                              void* d_out, int out_size)
{
    const float* feats = (const float*)d_in[0];
    const int*   nidx  = (const int*)d_in[1];
    const int*   nmask = (const int*)d_in[2];
    const float* W1    = (const float*)d_in[3];
    const float* b1    = (const float*)d_in[4];
    const float* a1    = (const float*)d_in[5];
    const float* W2    = (const float*)d_in[6];
    const float* b2    = (const float*)d_in[7];
    const float* a2    = (const float*)d_in[8];
    float* out = (float*)d_out;

    float  *dump = nullptr;
    __half *hfeats = nullptr, *scr = nullptr, *wh = nullptr;
    cudaGetSymbolAddress((void**)&dump,   g_dump);
    cudaGetSymbolAddress((void**)&hfeats, g_hfeats);
    cudaGetSymbolAddress((void**)&scr,    g_scr);
    cudaGetSymbolAddress((void**)&wh,     g_wh);

    cudaFuncSetAttribute(conv_kernel,
                         cudaFuncAttributeMaxDynamicSharedMemorySize, SMEM_BYTES);

    const int WN2 = KOFF * CHN * CHN / 2;             // 124416
    tohalf_kernel<<<128, 256>>>((const float2*)W1, (__half2*)wh, WN2);
    tohalf_kernel<<<128, 256>>>((const float2*)W2, (__half2*)(wh + (size_t)KOFF * CHN * CHN), WN2);
    tohalf_kernel<<<2048, 256>>>((const float2*)feats, (__half2*)hfeats, NPTS * CHN / 2);

    const int grid = NPTS / MT;  // 512
    conv_kernel<<<grid, NTHR, SMEM_BYTES>>>(hfeats, nidx, nmask, wh, dump);
    epi1_kernel<<<2048, 256>>>((const float4*)dump, b1, a1, (uint2*)scr);
    conv_kernel<<<grid, NTHR, SMEM_BYTES>>>(scr, nidx, nmask,
                                            wh + (size_t)KOFF * CHN * CHN, out);
    epi2_kernel<<<2048, 256>>>((float4*)out, (const float4*)feats, b2, a2);
}